// round 15
// baseline (speedup 1.0000x reference)
#include <cuda_runtime.h>
#include <cstdint>

// Problem constants
#define BATCH 16384
#define NN    1024
#define NI    128
#define NO    64
#define REFRACTORY 0.9f

#define KC       64
#define NCHUNK   (NN / KC)          // 16
#define MT       64                 // rows per CTA
#define NTHREADS 160                // 4 consumer warps + 1 producer warp
#define GRID     (BATCH / MT)       // 256
#define STAGES   3

// ---- dynamic smem layout ----
// [0,48)    mbarriers: per stage {full, empty} pairs (16B/stage)
// [1024+)   ring of 3 stages: A 16KB (swizzled) + B 16KB (packed image)
#define SM_MBAR     0
#define A_BYTES     16384
#define B_BYTES     16384
#define STAGE_BYTES (A_BYTES + B_BYTES)          // 32768
#define SM_BUF      1024
#define SMEM_TOTAL  (SM_BUF + STAGES * STAGE_BYTES)   // 99328

// B packed image (16KB per chunk), tf32-rounded, refractory-folded:
// uint4 idx within chunk = (ks*4 + ntp)*32 + lane ; 4 floats =
//   {nt=2ntp:k, nt=2ntp:k+4, nt=2ntp+1:k, nt=2ntp+1:k+4}
//   k = chunk*64 + ks*8 + (lane&3),  n = nt*8 + (lane>>2)
__device__ __align__(16) float g_Bpack[NCHUNK * 8 * 4 * 32 * 4];

__device__ __forceinline__ uint32_t smem_u32(const void* p) {
    uint32_t a;
    asm("{ .reg .u64 t; cvta.to.shared.u64 t, %1; cvt.u32.u64 %0, t; }" : "=r"(a) : "l"(p));
    return a;
}
__device__ __forceinline__ void ldm_x4(uint32_t* r, uint32_t addr) {
    asm volatile("ldmatrix.sync.aligned.m8n8.x4.shared.b16 {%0,%1,%2,%3}, [%4];"
                 : "=r"(r[0]), "=r"(r[1]), "=r"(r[2]), "=r"(r[3]) : "r"(addr));
}
__device__ __forceinline__ void mma_tf32(float* d, const uint32_t* a, uint32_t b0, uint32_t b1) {
    asm volatile(
        "mma.sync.aligned.m16n8k8.row.col.f32.tf32.tf32.f32 "
        "{%0,%1,%2,%3}, {%4,%5,%6,%7}, {%8,%9}, {%0,%1,%2,%3};"
        : "+f"(d[0]), "+f"(d[1]), "+f"(d[2]), "+f"(d[3])
        : "r"(a[0]), "r"(a[1]), "r"(a[2]), "r"(a[3]), "r"(b0), "r"(b1));
}
__device__ __forceinline__ uint32_t cvt_tf32(uint32_t x) {
    uint32_t d;
    asm("cvt.rna.tf32.f32 %0, %1;" : "=r"(d) : "f"(__uint_as_float(x)));
    return d;
}
__device__ __forceinline__ void cp_async16(uint32_t smem_addr, const void* gptr) {
    asm volatile("cp.async.cg.shared.global [%0], [%1], 16;"
                 :: "r"(smem_addr), "l"(gptr) : "memory");
}
// On completion of ALL prior cp.async by this thread: arrive (noinc) on mbarrier
__device__ __forceinline__ void cp_async_mbar_arrive(uint32_t mbar) {
    asm volatile("cp.async.mbarrier.arrive.noinc.shared.b64 [%0];" :: "r"(mbar) : "memory");
}
#define MBARRIER_INIT(sm, c) \
    asm volatile("mbarrier.init.shared.b64 [%0], %1;" :: "r"(sm), "r"((uint32_t)(c)) : "memory")
#define MBARRIER_ARRIVE(sm) \
    asm volatile("mbarrier.arrive.shared.b64 _, [%0];" :: "r"(sm) : "memory")
#define CP_COMMIT() asm volatile("cp.async.commit_group;" ::: "memory")
#define CP_WAIT0()  asm volatile("cp.async.wait_group 0;" ::: "memory")

__device__ __forceinline__ void mbar_wait_parity(uint32_t mbar, uint32_t parity) {
    uint32_t done;
    asm volatile(
        "{ .reg .pred p;\n\t"
        "mbarrier.try_wait.parity.acquire.cta.shared::cta.b64 p, [%1], %2;\n\t"
        "selp.b32 %0, 1, 0, p; }"
        : "=r"(done) : "r"(mbar), "r"(parity) : "memory");
    if (!done) {
        asm volatile(
            "{ .reg .pred P1;\n\t"
            "WL_%=:\n\t"
            "mbarrier.try_wait.parity.acquire.cta.shared::cta.b64 P1, [%0], %1, 0x989680;\n\t"
            "@P1 bra.uni WD_%=;\n\t"
            "bra.uni WL_%=;\n\t"
            "WD_%=: }"
            :: "r"(mbar), "r"(parity) : "memory");
    }
}

// A stage: 64 rows x 16 units(16B); two 8KB halves (u<8 / u>=8), swizzled.
__device__ __forceinline__ uint32_t a_off(int row, int u) {
    return (uint32_t)(((u >> 3) << 13) + (row << 7) + (((u & 7) ^ (row & 7)) << 4));
}

// ---------------- prep: round + fold + pack weight slice ----------------
__global__ void prep_kernel(const float* __restrict__ W) {
    int idx = blockIdx.x * blockDim.x + threadIdx.x;   // 0..65535
    if (idx >= NN * NO) return;
    int j     = idx & 3;
    int lane  = (idx >> 2) & 31;
    int ntp   = (idx >> 7) & 3;
    int ks    = (idx >> 9) & 7;
    int chunk = idx >> 12;
    int nt = 2 * ntp + (j >> 1);
    int k  = chunk * 64 + ks * 8 + (lane & 3) + (j & 1) * 4;
    int n  = nt * 8 + (lane >> 2);
    float f = (k >= NI && k < NN - NO) ? REFRACTORY : 1.0f;
    float val = W[(size_t)k * NN + (NN - NO) + n] * f;
    g_Bpack[idx] = __uint_as_float(cvt_tf32(__float_as_uint(val)));
}

// ---------------- activation ----------------
__device__ __forceinline__ float activate(float x, int a) {
    if (a == 0) return fmaxf(x, 0.0f);
    if (a == 1) { float r; asm("tanh.approx.f32 %0, %1;" : "=f"(r) : "f"(x)); return r; }
    if (a == 2) {
        float e, r;
        asm("ex2.approx.f32 %0, %1;" : "=f"(e) : "f"(-1.4426950408889634f * x));
        asm("rcp.approx.f32 %0, %1;" : "=f"(r) : "f"(1.0f + e));
        return r;
    }
    return x;
}

// ---------------- main kernel: producer warp + 4 consumer warps ----------------
__global__ void __launch_bounds__(NTHREADS, 2)
nn_tf32_kernel(const float* __restrict__ prev,    // [B, N]
               const float* __restrict__ inp,     // [B, I]
               const float* __restrict__ biases,  // [N]
               const int*   __restrict__ act,     // [N]
               float* __restrict__ out)           // [B, O]
{
    extern __shared__ unsigned char smem[];
    const uint32_t sb = smem_u32(smem);
    const int tid  = threadIdx.x;
    const int lane = tid & 31;
    const int wid  = tid >> 5;          // 0..3 consumers, 4 producer
    const int row0 = blockIdx.x * MT;

    // mbarriers: full[s] = sb + s*16, empty[s] = sb + s*16 + 8
    if (tid == 0) {
#pragma unroll
        for (int s = 0; s < STAGES; ++s) {
            MBARRIER_INIT(sb + SM_MBAR + s * 16, 32);      // full: 32 async arrivals
            MBARRIER_INIT(sb + SM_MBAR + s * 16 + 8, 4);   // empty: 4 consumer warps
        }
    }
    __syncthreads();

    if (wid == 4) {
        // ======== PRODUCER ========
        int ps = 0, pph = 1;                     // first empty-wait passes
        for (int c = 0; c < NCHUNK; ++c) {
            mbar_wait_parity(sb + SM_MBAR + ps * 16 + 8, pph);
            const uint32_t stage = sb + SM_BUF + ps * STAGE_BYTES;
            const float* src;
            int ldx;
            if (c < 2) { src = inp  + (size_t)row0 * NI + c * KC; ldx = NI; }
            else       { src = prev + (size_t)row0 * NN + c * KC; ldx = NN; }
            // A: 1024 x 16B, half-warp per 256B row segment
#pragma unroll
            for (int i = 0; i < 32; ++i) {
                int g = lane + i * 32;
                int row = g >> 4, u = g & 15;
                cp_async16(stage + a_off(row, u), src + (size_t)row * ldx + u * 4);
            }
            // B: 16KB contiguous packed image
            const float* bsrc = g_Bpack + (size_t)c * 4096;
#pragma unroll
            for (int i = 0; i < 32; ++i) {
                int g = lane + i * 32;
                cp_async16(stage + A_BYTES + g * 16, bsrc + g * 4);
            }
            cp_async_mbar_arrive(sb + SM_MBAR + ps * 16);   // full[s] on completion
            if (++ps == STAGES) { ps = 0; pph ^= 1; }
        }
        CP_COMMIT(); CP_WAIT0();                 // drain before exit
    } else {
        // ======== CONSUMERS (4 warps x 16 rows, all 64 cols) ========
        float acc[8][4];
#pragma unroll
        for (int nt = 0; nt < 8; ++nt)
#pragma unroll
            for (int i = 0; i < 4; ++i) acc[nt][i] = 0.0f;

        const int arow = wid * 16 + (lane & 15);
        const int auhi = lane >> 4;
        int cs = 0, cph = 0;

        for (int c = 0; c < NCHUNK; ++c) {
            mbar_wait_parity(sb + SM_MBAR + cs * 16, cph);   // full[s]
            const uint32_t stage = sb + SM_BUF + cs * STAGE_BYTES;
            const uint32_t bbase = stage + A_BYTES + lane * 16;

            uint4 bq[4];
#pragma unroll
            for (int t = 0; t < 4; ++t)
                bq[t] = *(const uint4*)(smem + (bbase - sb) + t * 512);

#pragma unroll
            for (int ks = 0; ks < 8; ++ks) {
                uint4 bn[4];
                if (ks < 7) {
                    uint32_t bnext = (bbase - sb) + (ks + 1) * 2048;
#pragma unroll
                    for (int t = 0; t < 4; ++t)
                        bn[t] = *(const uint4*)(smem + bnext + t * 512);
                }
                uint32_t a[4];
                ldm_x4(a, stage + a_off(arow, 2 * ks + auhi));
#pragma unroll
                for (int q = 0; q < 4; ++q) a[q] = cvt_tf32(a[q]);
#pragma unroll
                for (int ntp = 0; ntp < 4; ++ntp) {
                    mma_tf32(acc[2 * ntp + 0], a, bq[ntp].x, bq[ntp].y);
                    mma_tf32(acc[2 * ntp + 1], a, bq[ntp].z, bq[ntp].w);
                }
#pragma unroll
                for (int t = 0; t < 4; ++t) bq[t] = bn[t];
            }

            if (lane == 0) MBARRIER_ARRIVE(sb + SM_MBAR + cs * 16 + 8);  // empty[s]
            if (++cs == STAGES) { cs = 0; cph ^= 1; }
        }

        // ---- epilogue: bias + heterogeneous activation + store ----
        const int rg = row0 + wid * 16 + (lane >> 2);
#pragma unroll
        for (int nt = 0; nt < 8; ++nt) {
            int col = nt * 8 + (lane & 3) * 2;
            float b0 = __ldg(biases + NN - NO + col);
            float b1 = __ldg(biases + NN - NO + col + 1);
            int   a0 = __ldg(act + NN - NO + col);
            int   a1 = __ldg(act + NN - NO + col + 1);
            float2 o;
            o.x = activate(acc[nt][0] + b0, a0);
            o.y = activate(acc[nt][1] + b1, a1);
            *(float2*)(out + (size_t)rg * NO + col) = o;
            o.x = activate(acc[nt][2] + b0, a0);
            o.y = activate(acc[nt][3] + b1, a1);
            *(float2*)(out + (size_t)(rg + 8) * NO + col) = o;
        }
    }
}

extern "C" void kernel_launch(void* const* d_in, const int* in_sizes, int n_in,
                              void* d_out, int out_size) {
    (void)in_sizes; (void)n_in; (void)out_size;
    const float* prev   = (const float*)d_in[0];  // [16384,1024]
    const float* inp    = (const float*)d_in[1];  // [16384,128]
    const float* W      = (const float*)d_in[2];  // [1024,1024]
    const float* biases = (const float*)d_in[3];  // [1024]
    const int*   act    = (const int*)d_in[4];    // [1024]
    float* out = (float*)d_out;                   // [16384,64]

    cudaFuncSetAttribute(nn_tf32_kernel, cudaFuncAttributeMaxDynamicSharedMemorySize, SMEM_TOTAL);

    prep_kernel<<<256, 256>>>(W);
    nn_tf32_kernel<<<GRID, NTHREADS, SMEM_TOTAL>>>(prev, inp, biases, act, out);
}